// round 2
// baseline (speedup 1.0000x reference)
#include <cuda_runtime.h>
#include <math_constants.h>

// Problem dims (fixed by reference)
#define Bb  4
#define Tt  2048
#define Dd  1024
#define Hh  16
#define HDd 64
#define Mtot (Bb * Tt)   // 8192

// Scratch: __device__ globals (no allocation allowed in kernel_launch)
__device__ float g_qp[Bb * Hh * Tt * HDd];  // [B,H,T,HD]
__device__ float g_kp[Bb * Hh * Tt * HDd];  // [B,H,T,HD]
__device__ float g_vp[Bb * Hh * Tt * HDd];  // [B,H,T,HD]
__device__ float g_ao[Bb * Tt * Dd];        // [B,T,D] (attention out, pre-Wo)

// ---------------------------------------------------------------------------
// GEMM: out[m,n] = sum_k A[m,k] * W[n,k] + bias[n]
// A: [M, K=1024] row-major, W: [N=1024, K=1024] row-major (torch Linear W)
// BM=BN=128, BK=8, 256 threads, 8x8 microtile per thread.
// Double-buffered smem + register prefetch: LDG(k+1) issued before compute(k),
// STS after compute, ONE __syncthreads per k-step. Load latency fully hidden.
// split==1: write head-split layout [B,H,T,HD]; split==0: plain [M, 1024].
// ---------------------------------------------------------------------------
__global__ __launch_bounds__(256)
void gemm_kernel(const float* __restrict__ A, const float* __restrict__ W,
                 const float* __restrict__ bias, float* __restrict__ out,
                 int split)
{
    __shared__ float As[2][8][128];
    __shared__ float Bs[2][8][128];

    const int tid = threadIdx.x;
    const int tx  = tid & 15;    // 0..15 -> N microtiles
    const int ty  = tid >> 4;    // 0..15 -> M microtiles
    const int bm  = blockIdx.y * 128;
    const int bn  = blockIdx.x * 128;

    // Global load mapping: each thread loads one float4 from A and one from W
    const int lr = tid >> 1;          // 0..127 (tile row)
    const int lk = (tid & 1) * 4;     // 0 or 4 (k offset)

    const float* Ap = A + (size_t)(bm + lr) * Dd + lk;
    const float* Wp = W + (size_t)(bn + lr) * Dd + lk;

    // Prologue: load k-tile 0 into buffer 0
    {
        float4 av = *(const float4*)Ap;
        float4 wv = *(const float4*)Wp;
        As[0][lk + 0][lr] = av.x; As[0][lk + 1][lr] = av.y;
        As[0][lk + 2][lr] = av.z; As[0][lk + 3][lr] = av.w;
        Bs[0][lk + 0][lr] = wv.x; Bs[0][lk + 1][lr] = wv.y;
        Bs[0][lk + 2][lr] = wv.z; Bs[0][lk + 3][lr] = wv.w;
    }
    __syncthreads();

    float acc[8][8];
    #pragma unroll
    for (int i = 0; i < 8; i++)
        #pragma unroll
        for (int j = 0; j < 8; j++) acc[i][j] = 0.f;

    #pragma unroll 1
    for (int k0 = 0; k0 < Dd; k0 += 8) {
        const int buf = (k0 >> 3) & 1;
        const bool more = (k0 + 8) < Dd;

        // Prefetch next k-tile into registers (latency hidden by compute below)
        float4 av2, wv2;
        if (more) {
            av2 = *(const float4*)(Ap + k0 + 8);
            wv2 = *(const float4*)(Wp + k0 + 8);
        }

        #pragma unroll
        for (int kk = 0; kk < 8; kk++) {
            float a[8], b[8];
            *(float4*)(a)     = *(const float4*)&As[buf][kk][ty * 8];
            *(float4*)(a + 4) = *(const float4*)&As[buf][kk][ty * 8 + 4];
            *(float4*)(b)     = *(const float4*)&Bs[buf][kk][tx * 8];
            *(float4*)(b + 4) = *(const float4*)&Bs[buf][kk][tx * 8 + 4];
            #pragma unroll
            for (int i = 0; i < 8; i++)
                #pragma unroll
                for (int j = 0; j < 8; j++)
                    acc[i][j] += a[i] * b[j];
        }

        if (more) {
            const int nb = buf ^ 1;
            As[nb][lk + 0][lr] = av2.x; As[nb][lk + 1][lr] = av2.y;
            As[nb][lk + 2][lr] = av2.z; As[nb][lk + 3][lr] = av2.w;
            Bs[nb][lk + 0][lr] = wv2.x; Bs[nb][lk + 1][lr] = wv2.y;
            Bs[nb][lk + 2][lr] = wv2.z; Bs[nb][lk + 3][lr] = wv2.w;
            __syncthreads();
        }
    }

    // Epilogue
    #pragma unroll
    for (int i = 0; i < 8; i++) {
        const int m = bm + ty * 8 + i;
        const int bb = m / Tt;
        const int t  = m % Tt;
        #pragma unroll
        for (int j = 0; j < 8; j++) {
            const int n = bn + tx * 8 + j;
            const float v = acc[i][j] + bias[n];
            if (split) {
                const int h  = n >> 6;       // n / HD
                const int hd = n & 63;       // n % HD
                out[(((size_t)(bb * Hh + h) * Tt) + t) * HDd + hd] = v;
            } else {
                out[(size_t)m * Dd + n] = v;
            }
        }
    }
}

// ---------------------------------------------------------------------------
// Fused attention: per CTA one (b, h, 64-row Q tile). Online softmax over
// 64-row K/V tiles. 256 threads = 16x16; each thread owns a 4x4 of S and a
// 4x4 of O (O cols = tx*4..tx*4+3 of HD=64).
// K/V tiles register-prefetched one iteration ahead: LDG(kt+1) issued right
// after STS(kt), consumed at next iteration's STS -> latency overlapped with
// S-compute + softmax + PV.
// Smem: Qs [d][row] (scaled), KP [d][row] as K then reused as Ps [row][col],
// Vs [row][d]. 3 * 16KB = 48KB static.
// ---------------------------------------------------------------------------
__global__ __launch_bounds__(256)
void attn_kernel(const float* __restrict__ qp, const float* __restrict__ kp,
                 const float* __restrict__ vp, float* __restrict__ ao)
{
    __shared__ float Qs[64][64];   // [d][row], pre-scaled by 1/sqrt(HD)
    __shared__ float KP[64][64];   // K as [d][row]; reused as P [row][col]
    __shared__ float Vs[64][64];   // [row][d]

    const int tid = threadIdx.x;
    const int tx  = tid & 15;
    const int ty  = tid >> 4;
    const int qt = blockIdx.x, h = blockIdx.y, b = blockIdx.z;

    const float* Qg = qp + ((size_t)(b * Hh + h) * Tt + qt * 64) * HDd;
    const float* Kg = kp + ((size_t)(b * Hh + h) * Tt) * HDd;
    const float* Vg = vp + ((size_t)(b * Hh + h) * Tt) * HDd;

    const int lrow = tid >> 2;          // 0..63
    const int ld0  = (tid & 3) * 16;    // 0,16,32,48

    // Load Q tile transposed + scaled
    #pragma unroll
    for (int u = 0; u < 4; u++) {
        float4 t = *(const float4*)(Qg + lrow * HDd + ld0 + u * 4);
        Qs[ld0 + u * 4 + 0][lrow] = t.x * 0.125f;
        Qs[ld0 + u * 4 + 1][lrow] = t.y * 0.125f;
        Qs[ld0 + u * 4 + 2][lrow] = t.z * 0.125f;
        Qs[ld0 + u * 4 + 3][lrow] = t.w * 0.125f;
    }

    // Preload K/V tile 0 into registers
    float4 kreg[4], vreg[4];
    #pragma unroll
    for (int u = 0; u < 4; u++) {
        kreg[u] = *(const float4*)(Kg + lrow * HDd + ld0 + u * 4);
        vreg[u] = *(const float4*)(Vg + lrow * HDd + ld0 + u * 4);
    }

    float m[4], l[4], o[4][4];
    #pragma unroll
    for (int i = 0; i < 4; i++) {
        m[i] = -CUDART_INF_F; l[i] = 0.f;
        #pragma unroll
        for (int j = 0; j < 4; j++) o[i][j] = 0.f;
    }

    for (int kt = 0; kt < Tt / 64; kt++) {
        __syncthreads();  // A: previous iteration's PV readers of KP/Vs done

        // Stage current K/V tile from registers to smem
        #pragma unroll
        for (int u = 0; u < 4; u++) {
            KP[ld0 + u * 4 + 0][lrow] = kreg[u].x;
            KP[ld0 + u * 4 + 1][lrow] = kreg[u].y;
            KP[ld0 + u * 4 + 2][lrow] = kreg[u].z;
            KP[ld0 + u * 4 + 3][lrow] = kreg[u].w;
            *(float4*)&Vs[lrow][ld0 + u * 4] = vreg[u];
        }
        __syncthreads();  // B: tiles visible (also covers Qs on first iter)

        // Prefetch next K/V tile (overlaps with S + softmax + PV below)
        if (kt + 1 < Tt / 64) {
            const float* Kt = Kg + (size_t)(kt + 1) * 64 * HDd;
            const float* Vt = Vg + (size_t)(kt + 1) * 64 * HDd;
            #pragma unroll
            for (int u = 0; u < 4; u++) {
                kreg[u] = *(const float4*)(Kt + lrow * HDd + ld0 + u * 4);
                vreg[u] = *(const float4*)(Vt + lrow * HDd + ld0 + u * 4);
            }
        }

        // S = Q K^T (scaled): 4x4 per thread
        float s[4][4];
        #pragma unroll
        for (int i = 0; i < 4; i++)
            #pragma unroll
            for (int j = 0; j < 4; j++) s[i][j] = 0.f;

        #pragma unroll 16
        for (int d = 0; d < 64; d++) {
            float4 qv = *(const float4*)&Qs[d][ty * 4];
            float4 kv = *(const float4*)&KP[d][tx * 4];
            float qa[4] = {qv.x, qv.y, qv.z, qv.w};
            float ka[4] = {kv.x, kv.y, kv.z, kv.w};
            #pragma unroll
            for (int i = 0; i < 4; i++)
                #pragma unroll
                for (int j = 0; j < 4; j++)
                    s[i][j] += qa[i] * ka[j];
        }

        __syncthreads();  // C: all K reads finished before P overwrites KP

        // Online softmax update + stash P into KP as [row][col]
        #pragma unroll
        for (int i = 0; i < 4; i++) {
            float mx = fmaxf(fmaxf(s[i][0], s[i][1]), fmaxf(s[i][2], s[i][3]));
            #pragma unroll
            for (int off = 8; off >= 1; off >>= 1)
                mx = fmaxf(mx, __shfl_xor_sync(0xffffffffu, mx, off));
            const float mnew = fmaxf(m[i], mx);
            const float corr = __expf(m[i] - mnew);
            float4 p;
            p.x = __expf(s[i][0] - mnew);
            p.y = __expf(s[i][1] - mnew);
            p.z = __expf(s[i][2] - mnew);
            p.w = __expf(s[i][3] - mnew);
            float sum = p.x + p.y + p.z + p.w;
            #pragma unroll
            for (int off = 8; off >= 1; off >>= 1)
                sum += __shfl_xor_sync(0xffffffffu, sum, off);
            l[i] = l[i] * corr + sum;
            m[i] = mnew;
            #pragma unroll
            for (int j = 0; j < 4; j++) o[i][j] *= corr;
            *(float4*)&KP[ty * 4 + i][tx * 4] = p;
        }
        __syncthreads();  // D: P visible

        // O += P V  (P in KP as [row][col], V as [row][d])
        #pragma unroll 8
        for (int j4 = 0; j4 < 16; j4++) {
            float4 vv[4];
            #pragma unroll
            for (int u = 0; u < 4; u++)
                vv[u] = *(const float4*)&Vs[j4 * 4 + u][tx * 4];
            #pragma unroll
            for (int i = 0; i < 4; i++) {
                float4 pv = *(const float4*)&KP[ty * 4 + i][j4 * 4];
                o[i][0] += pv.x * vv[0].x; o[i][1] += pv.x * vv[0].y;
                o[i][2] += pv.x * vv[0].z; o[i][3] += pv.x * vv[0].w;
                o[i][0] += pv.y * vv[1].x; o[i][1] += pv.y * vv[1].y;
                o[i][2] += pv.y * vv[1].z; o[i][3] += pv.y * vv[1].w;
                o[i][0] += pv.z * vv[2].x; o[i][1] += pv.z * vv[2].y;
                o[i][2] += pv.z * vv[2].z; o[i][3] += pv.z * vv[2].w;
                o[i][0] += pv.w * vv[3].x; o[i][1] += pv.w * vv[3].y;
                o[i][2] += pv.w * vv[3].z; o[i][3] += pv.w * vv[3].w;
            }
        }
    }

    // Finalize and write [B,T,D] (merge heads in-place)
    #pragma unroll
    for (int i = 0; i < 4; i++) {
        const float inv = 1.f / l[i];
        float4 r;
        r.x = o[i][0] * inv; r.y = o[i][1] * inv;
        r.z = o[i][2] * inv; r.w = o[i][3] * inv;
        const int t = qt * 64 + ty * 4 + i;
        float* dst = ao + ((size_t)(b * Tt + t)) * Dd + h * HDd + tx * 4;
        *(float4*)dst = r;
    }
}

// ---------------------------------------------------------------------------
extern "C" void kernel_launch(void* const* d_in, const int* in_sizes, int n_in,
                              void* d_out, int out_size)
{
    const float* q  = (const float*)d_in[0];
    const float* k  = (const float*)d_in[1];
    const float* v  = (const float*)d_in[2];
    const float* Wq = (const float*)d_in[3];
    const float* bq = (const float*)d_in[4];
    const float* Wk = (const float*)d_in[5];
    const float* bk = (const float*)d_in[6];
    const float* Wv = (const float*)d_in[7];
    const float* bv = (const float*)d_in[8];
    const float* Wo = (const float*)d_in[9];
    const float* bo = (const float*)d_in[10];

    float *qp, *kp, *vp, *ao;
    cudaGetSymbolAddress((void**)&qp, g_qp);
    cudaGetSymbolAddress((void**)&kp, g_kp);
    cudaGetSymbolAddress((void**)&vp, g_vp);
    cudaGetSymbolAddress((void**)&ao, g_ao);

    dim3 gblk(256);
    dim3 ggrid(Dd / 128, Mtot / 128);   // (8, 64)

    // Q/K/V projections with fused head-split epilogue
    gemm_kernel<<<ggrid, gblk>>>(q, Wq, bq, qp, 1);
    gemm_kernel<<<ggrid, gblk>>>(k, Wk, bk, kp, 1);
    gemm_kernel<<<ggrid, gblk>>>(v, Wv, bv, vp, 1);

    // Fused flash attention
    dim3 agrid(Tt / 64, Hh, Bb);        // (32, 16, 4)
    attn_kernel<<<agrid, 256>>>(qp, kp, vp, ao);

    // Output projection -> d_out
    gemm_kernel<<<ggrid, gblk>>>(ao, Wo, bo, (float*)d_out, 0);
}

// round 3
// speedup vs baseline: 1.5308x; 1.5308x over previous
#include <cuda_runtime.h>
#include <math_constants.h>
#include <cstdint>

// Problem dims (fixed by reference)
#define Bb  4
#define Tt  2048
#define Dd  1024
#define Hh  16
#define HDd 64
#define Mtot (Bb * Tt)   // 8192

// Scratch: __device__ globals (no allocation allowed in kernel_launch)
__device__ float g_qp[Bb * Hh * Tt * HDd];  // [B,H,T,HD]
__device__ float g_kp[Bb * Hh * Tt * HDd];  // [B,H,T,HD]
__device__ float g_vp[Bb * Hh * Tt * HDd];  // [B,H,T,HD]
__device__ float g_ao[Bb * Tt * Dd];        // [B,T,D] (attention out, pre-Wo)

// ---------------------------------------------------------------------------
// tf32 helpers
// ---------------------------------------------------------------------------
__device__ __forceinline__ uint32_t f2tf32(float x) {
    uint32_t r;
    asm("cvt.rna.tf32.f32 %0, %1;" : "=r"(r) : "f"(x));
    return r;
}

__device__ __forceinline__ void mma_tf32(float c[4],
                                         uint32_t a0, uint32_t a1, uint32_t a2, uint32_t a3,
                                         uint32_t b0, uint32_t b1) {
    asm("mma.sync.aligned.m16n8k8.row.col.f32.tf32.tf32.f32 "
        "{%0,%1,%2,%3}, {%4,%5,%6,%7}, {%8,%9}, {%0,%1,%2,%3};"
        : "+f"(c[0]), "+f"(c[1]), "+f"(c[2]), "+f"(c[3])
        : "r"(a0), "r"(a1), "r"(a2), "r"(a3), "r"(b0), "r"(b1));
}

// ---------------------------------------------------------------------------
// tf32 tensor-core GEMM: out[m,n] = sum_k A[m,k] * W[n,k] + bias[n]
// A: [M, K=1024] row-major, W: [N=1024, K=1024] row-major (torch Linear W).
// CTA tile 128x128, BK=16, 256 threads = 8 warps, warp tile 32x64
// (warps: 4 along M x 2 along N). Per warp per k8-step: 2 m-tiles x 8 n-tiles
// mma.m16n8k8. Smem pitch 20 floats -> conflict-free fragment loads.
// Double-buffered smem + register prefetch, one __syncthreads per k-step.
// tf32 conversion (cvt.rna) done once at the STS stage.
// split==1: write head-split layout [B,H,T,HD]; split==0: plain [M, 1024].
// ---------------------------------------------------------------------------
#define GP 20   // smem row pitch (16 + 4 pad)

__global__ __launch_bounds__(256)
void gemm_tc_kernel(const float* __restrict__ A, const float* __restrict__ W,
                    const float* __restrict__ bias, float* __restrict__ out,
                    int split)
{
    __shared__ uint32_t As[2][128 * GP];
    __shared__ uint32_t Ws[2][128 * GP];

    const int tid  = threadIdx.x;
    const int wid  = tid >> 5;
    const int lane = tid & 31;
    const int l4   = lane >> 2;   // 0..7  (row group)
    const int lm4  = lane & 3;    // 0..3  (k within quad)

    const int wm = (wid & 3) * 32;   // warp M offset in CTA tile
    const int wn = (wid >> 2) * 64;  // warp N offset in CTA tile

    const int bm = blockIdx.y * 128;
    const int bn = blockIdx.x * 128;

    // Global->smem staging map: 512 float4 per 128x16 tile, 2 per thread
    const int r0 = tid >> 2;               // idx = tid    -> row
    const int c0 = (tid & 3) * 4;          // float4 col
    const int r1 = (tid + 256) >> 2;       // idx = tid+256
    const int c1 = ((tid + 256) & 3) * 4;

    const float* Ap0 = A + (size_t)(bm + r0) * Dd + c0;
    const float* Ap1 = A + (size_t)(bm + r1) * Dd + c1;
    const float* Wp0 = W + (size_t)(bn + r0) * Dd + c0;
    const float* Wp1 = W + (size_t)(bn + r1) * Dd + c1;

    // Prologue: stage k-tile 0 into buffer 0 (with tf32 rounding)
    {
        float4 a0 = *(const float4*)Ap0;
        float4 a1 = *(const float4*)Ap1;
        float4 w0 = *(const float4*)Wp0;
        float4 w1 = *(const float4*)Wp1;
        uint32_t* Asp = As[0];
        uint32_t* Wsp = Ws[0];
        Asp[r0 * GP + c0 + 0] = f2tf32(a0.x); Asp[r0 * GP + c0 + 1] = f2tf32(a0.y);
        Asp[r0 * GP + c0 + 2] = f2tf32(a0.z); Asp[r0 * GP + c0 + 3] = f2tf32(a0.w);
        Asp[r1 * GP + c1 + 0] = f2tf32(a1.x); Asp[r1 * GP + c1 + 1] = f2tf32(a1.y);
        Asp[r1 * GP + c1 + 2] = f2tf32(a1.z); Asp[r1 * GP + c1 + 3] = f2tf32(a1.w);
        Wsp[r0 * GP + c0 + 0] = f2tf32(w0.x); Wsp[r0 * GP + c0 + 1] = f2tf32(w0.y);
        Wsp[r0 * GP + c0 + 2] = f2tf32(w0.z); Wsp[r0 * GP + c0 + 3] = f2tf32(w0.w);
        Wsp[r1 * GP + c1 + 0] = f2tf32(w1.x); Wsp[r1 * GP + c1 + 1] = f2tf32(w1.y);
        Wsp[r1 * GP + c1 + 2] = f2tf32(w1.z); Wsp[r1 * GP + c1 + 3] = f2tf32(w1.w);
    }
    __syncthreads();

    float acc[2][8][4];
    #pragma unroll
    for (int mt = 0; mt < 2; mt++)
        #pragma unroll
        for (int nt = 0; nt < 8; nt++)
            #pragma unroll
            for (int r = 0; r < 4; r++) acc[mt][nt][r] = 0.f;

    #pragma unroll 1
    for (int k0 = 0; k0 < Dd; k0 += 16) {
        const int buf = (k0 >> 4) & 1;
        const bool more = (k0 + 16) < Dd;

        // Prefetch next k-tile into registers
        float4 pa0, pa1, pw0, pw1;
        if (more) {
            pa0 = *(const float4*)(Ap0 + k0 + 16);
            pa1 = *(const float4*)(Ap1 + k0 + 16);
            pw0 = *(const float4*)(Wp0 + k0 + 16);
            pw1 = *(const float4*)(Wp1 + k0 + 16);
        }

        const uint32_t* Asb = As[buf];
        const uint32_t* Wsb = Ws[buf];

        #pragma unroll
        for (int ks = 0; ks < 16; ks += 8) {
            // A fragments: 2 m-tiles
            uint32_t af[2][4];
            #pragma unroll
            for (int mt = 0; mt < 2; mt++) {
                const int rA = wm + mt * 16 + l4;
                af[mt][0] = Asb[(rA)     * GP + ks + lm4];
                af[mt][1] = Asb[(rA + 8) * GP + ks + lm4];
                af[mt][2] = Asb[(rA)     * GP + ks + lm4 + 4];
                af[mt][3] = Asb[(rA + 8) * GP + ks + lm4 + 4];
            }
            // B fragments: 8 n-tiles
            uint32_t bf[8][2];
            #pragma unroll
            for (int nt = 0; nt < 8; nt++) {
                const int rB = wn + nt * 8 + l4;
                bf[nt][0] = Wsb[rB * GP + ks + lm4];
                bf[nt][1] = Wsb[rB * GP + ks + lm4 + 4];
            }
            #pragma unroll
            for (int mt = 0; mt < 2; mt++)
                #pragma unroll
                for (int nt = 0; nt < 8; nt++)
                    mma_tf32(acc[mt][nt], af[mt][0], af[mt][1], af[mt][2], af[mt][3],
                             bf[nt][0], bf[nt][1]);
        }

        if (more) {
            const int nb = buf ^ 1;
            uint32_t* Asp = As[nb];
            uint32_t* Wsp = Ws[nb];
            Asp[r0 * GP + c0 + 0] = f2tf32(pa0.x); Asp[r0 * GP + c0 + 1] = f2tf32(pa0.y);
            Asp[r0 * GP + c0 + 2] = f2tf32(pa0.z); Asp[r0 * GP + c0 + 3] = f2tf32(pa0.w);
            Asp[r1 * GP + c1 + 0] = f2tf32(pa1.x); Asp[r1 * GP + c1 + 1] = f2tf32(pa1.y);
            Asp[r1 * GP + c1 + 2] = f2tf32(pa1.z); Asp[r1 * GP + c1 + 3] = f2tf32(pa1.w);
            Wsp[r0 * GP + c0 + 0] = f2tf32(pw0.x); Wsp[r0 * GP + c0 + 1] = f2tf32(pw0.y);
            Wsp[r0 * GP + c0 + 2] = f2tf32(pw0.z); Wsp[r0 * GP + c0 + 3] = f2tf32(pw0.w);
            Wsp[r1 * GP + c1 + 0] = f2tf32(pw1.x); Wsp[r1 * GP + c1 + 1] = f2tf32(pw1.y);
            Wsp[r1 * GP + c1 + 2] = f2tf32(pw1.z); Wsp[r1 * GP + c1 + 3] = f2tf32(pw1.w);
            __syncthreads();
        }
    }

    // Epilogue: c0:(r, 2c) c1:(r, 2c+1) c2:(r+8, 2c) c3:(r+8, 2c+1)
    #pragma unroll
    for (int mt = 0; mt < 2; mt++) {
        #pragma unroll
        for (int half = 0; half < 2; half++) {
            const int m  = bm + wm + mt * 16 + half * 8 + l4;
            const int bb = m / Tt;
            const int t  = m % Tt;
            #pragma unroll
            for (int nt = 0; nt < 8; nt++) {
                const int n = bn + wn + nt * 8 + 2 * lm4;
                float v0 = acc[mt][nt][half * 2 + 0] + bias[n];
                float v1 = acc[mt][nt][half * 2 + 1] + bias[n + 1];
                if (split) {
                    const int h  = n >> 6;
                    const int hd = n & 63;
                    float* dst = out + (((size_t)(bb * Hh + h) * Tt) + t) * HDd + hd;
                    *(float2*)dst = make_float2(v0, v1);
                } else {
                    *(float2*)(out + (size_t)m * Dd + n) = make_float2(v0, v1);
                }
            }
        }
    }
}

// ---------------------------------------------------------------------------
// Fused attention (UNCHANGED from passing round-2 kernel).
// ---------------------------------------------------------------------------
__global__ __launch_bounds__(256)
void attn_kernel(const float* __restrict__ qp, const float* __restrict__ kp,
                 const float* __restrict__ vp, float* __restrict__ ao)
{
    __shared__ float Qs[64][64];   // [d][row], pre-scaled by 1/sqrt(HD)
    __shared__ float KP[64][64];   // K as [d][row]; reused as P [row][col]
    __shared__ float Vs[64][64];   // [row][d]

    const int tid = threadIdx.x;
    const int tx  = tid & 15;
    const int ty  = tid >> 4;
    const int qt = blockIdx.x, h = blockIdx.y, b = blockIdx.z;

    const float* Qg = qp + ((size_t)(b * Hh + h) * Tt + qt * 64) * HDd;
    const float* Kg = kp + ((size_t)(b * Hh + h) * Tt) * HDd;
    const float* Vg = vp + ((size_t)(b * Hh + h) * Tt) * HDd;

    const int lrow = tid >> 2;          // 0..63
    const int ld0  = (tid & 3) * 16;    // 0,16,32,48

    #pragma unroll
    for (int u = 0; u < 4; u++) {
        float4 t = *(const float4*)(Qg + lrow * HDd + ld0 + u * 4);
        Qs[ld0 + u * 4 + 0][lrow] = t.x * 0.125f;
        Qs[ld0 + u * 4 + 1][lrow] = t.y * 0.125f;
        Qs[ld0 + u * 4 + 2][lrow] = t.z * 0.125f;
        Qs[ld0 + u * 4 + 3][lrow] = t.w * 0.125f;
    }

    float4 kreg[4], vreg[4];
    #pragma unroll
    for (int u = 0; u < 4; u++) {
        kreg[u] = *(const float4*)(Kg + lrow * HDd + ld0 + u * 4);
        vreg[u] = *(const float4*)(Vg + lrow * HDd + ld0 + u * 4);
    }

    float m[4], l[4], o[4][4];
    #pragma unroll
    for (int i = 0; i < 4; i++) {
        m[i] = -CUDART_INF_F; l[i] = 0.f;
        #pragma unroll
        for (int j = 0; j < 4; j++) o[i][j] = 0.f;
    }

    for (int kt = 0; kt < Tt / 64; kt++) {
        __syncthreads();

        #pragma unroll
        for (int u = 0; u < 4; u++) {
            KP[ld0 + u * 4 + 0][lrow] = kreg[u].x;
            KP[ld0 + u * 4 + 1][lrow] = kreg[u].y;
            KP[ld0 + u * 4 + 2][lrow] = kreg[u].z;
            KP[ld0 + u * 4 + 3][lrow] = kreg[u].w;
            *(float4*)&Vs[lrow][ld0 + u * 4] = vreg[u];
        }
        __syncthreads();

        if (kt + 1 < Tt / 64) {
            const float* Kt = Kg + (size_t)(kt + 1) * 64 * HDd;
            const float* Vt = Vg + (size_t)(kt + 1) * 64 * HDd;
            #pragma unroll
            for (int u = 0; u < 4; u++) {
                kreg[u] = *(const float4*)(Kt + lrow * HDd + ld0 + u * 4);
                vreg[u] = *(const float4*)(Vt + lrow * HDd + ld0 + u * 4);
            }
        }

        float s[4][4];
        #pragma unroll
        for (int i = 0; i < 4; i++)
            #pragma unroll
            for (int j = 0; j < 4; j++) s[i][j] = 0.f;

        #pragma unroll 16
        for (int d = 0; d < 64; d++) {
            float4 qv = *(const float4*)&Qs[d][ty * 4];
            float4 kv = *(const float4*)&KP[d][tx * 4];
            float qa[4] = {qv.x, qv.y, qv.z, qv.w};
            float ka[4] = {kv.x, kv.y, kv.z, kv.w};
            #pragma unroll
            for (int i = 0; i < 4; i++)
                #pragma unroll
                for (int j = 0; j < 4; j++)
                    s[i][j] += qa[i] * ka[j];
        }

        __syncthreads();

        #pragma unroll
        for (int i = 0; i < 4; i++) {
            float mx = fmaxf(fmaxf(s[i][0], s[i][1]), fmaxf(s[i][2], s[i][3]));
            #pragma unroll
            for (int off = 8; off >= 1; off >>= 1)
                mx = fmaxf(mx, __shfl_xor_sync(0xffffffffu, mx, off));
            const float mnew = fmaxf(m[i], mx);
            const float corr = __expf(m[i] - mnew);
            float4 p;
            p.x = __expf(s[i][0] - mnew);
            p.y = __expf(s[i][1] - mnew);
            p.z = __expf(s[i][2] - mnew);
            p.w = __expf(s[i][3] - mnew);
            float sum = p.x + p.y + p.z + p.w;
            #pragma unroll
            for (int off = 8; off >= 1; off >>= 1)
                sum += __shfl_xor_sync(0xffffffffu, sum, off);
            l[i] = l[i] * corr + sum;
            m[i] = mnew;
            #pragma unroll
            for (int j = 0; j < 4; j++) o[i][j] *= corr;
            *(float4*)&KP[ty * 4 + i][tx * 4] = p;
        }
        __syncthreads();

        #pragma unroll 8
        for (int j4 = 0; j4 < 16; j4++) {
            float4 vv[4];
            #pragma unroll
            for (int u = 0; u < 4; u++)
                vv[u] = *(const float4*)&Vs[j4 * 4 + u][tx * 4];
            #pragma unroll
            for (int i = 0; i < 4; i++) {
                float4 pv = *(const float4*)&KP[ty * 4 + i][j4 * 4];
                o[i][0] += pv.x * vv[0].x; o[i][1] += pv.x * vv[0].y;
                o[i][2] += pv.x * vv[0].z; o[i][3] += pv.x * vv[0].w;
                o[i][0] += pv.y * vv[1].x; o[i][1] += pv.y * vv[1].y;
                o[i][2] += pv.y * vv[1].z; o[i][3] += pv.y * vv[1].w;
                o[i][0] += pv.z * vv[2].x; o[i][1] += pv.z * vv[2].y;
                o[i][2] += pv.z * vv[2].z; o[i][3] += pv.z * vv[2].w;
                o[i][0] += pv.w * vv[3].x; o[i][1] += pv.w * vv[3].y;
                o[i][2] += pv.w * vv[3].z; o[i][3] += pv.w * vv[3].w;
            }
        }
    }

    #pragma unroll
    for (int i = 0; i < 4; i++) {
        const float inv = 1.f / l[i];
        float4 r;
        r.x = o[i][0] * inv; r.y = o[i][1] * inv;
        r.z = o[i][2] * inv; r.w = o[i][3] * inv;
        const int t = qt * 64 + ty * 4 + i;
        float* dst = ao + ((size_t)(b * Tt + t)) * Dd + h * HDd + tx * 4;
        *(float4*)dst = r;
    }
}

// ---------------------------------------------------------------------------
extern "C" void kernel_launch(void* const* d_in, const int* in_sizes, int n_in,
                              void* d_out, int out_size)
{
    const float* q  = (const float*)d_in[0];
    const float* k  = (const float*)d_in[1];
    const float* v  = (const float*)d_in[2];
    const float* Wq = (const float*)d_in[3];
    const float* bq = (const float*)d_in[4];
    const float* Wk = (const float*)d_in[5];
    const float* bk = (const float*)d_in[6];
    const float* Wv = (const float*)d_in[7];
    const float* bv = (const float*)d_in[8];
    const float* Wo = (const float*)d_in[9];
    const float* bo = (const float*)d_in[10];

    float *qp, *kp, *vp, *ao;
    cudaGetSymbolAddress((void**)&qp, g_qp);
    cudaGetSymbolAddress((void**)&kp, g_kp);
    cudaGetSymbolAddress((void**)&vp, g_vp);
    cudaGetSymbolAddress((void**)&ao, g_ao);

    dim3 gblk(256);
    dim3 ggrid(Dd / 128, Mtot / 128);   // (8, 64)

    // Q/K/V projections with fused head-split epilogue (tf32 tensor cores)
    gemm_tc_kernel<<<ggrid, gblk>>>(q, Wq, bq, qp, 1);
    gemm_tc_kernel<<<ggrid, gblk>>>(k, Wk, bk, kp, 1);
    gemm_tc_kernel<<<ggrid, gblk>>>(v, Wv, bv, vp, 1);

    // Fused flash attention (fp32 SIMT)
    dim3 agrid(Tt / 64, Hh, Bb);        // (32, 16, 4)
    attn_kernel<<<agrid, 256>>>(qp, kp, vp, ao);

    // Output projection -> d_out (tf32 tensor cores)
    gemm_tc_kernel<<<ggrid, gblk>>>(ao, Wo, bo, (float*)d_out, 0);
}